// round 3
// baseline (speedup 1.0000x reference)
#include <cuda_runtime.h>

#define HID   2048
#define NEXP  64
#define NTOK  16384
#define SINK_TOL 1e-4
#define MAX_ITERS 512
#define GRIDB 148
#define TPB   256
#define TOKB  111   // ceil(NTOK / GRIDB); 148*111 = 16428 >= 16384

// libdevice exp — what XLA GPU emits for jnp.exp, immune to fast-math rewrite.
extern "C" __device__ float __nv_expf(float);

// Scratch (static device arrays — no allocations).
__device__ unsigned long long g_bar = 0ULL;              // monotonic grid barrier
__device__ float  g_C[(size_t)NTOK * NEXP];              // exp(logits) f32, 4 MB
__device__ double g_colsum[MAX_ITERS * NEXP];            // per-iteration column sums (f64)

// ---------------------------------------------------------------------------
// Kernel 1: logits GEMM.  f32 FFMA inside 32-term k-chunks, chunk partials
// accumulated in fp64 -> logit error ~2e-7 absolute (near-exact).
// C[t,e] = __nv_expf((float)logit64)  -- C deliberately f32 like the reference.
// ---------------------------------------------------------------------------
#define BM 128
#define BK 32

__global__ void __launch_bounds__(256)
gemm_exp_kernel(const float* __restrict__ X, const float* __restrict__ W)
{
    __shared__ float As[BM][BK + 4];
    __shared__ float Bs[BK][NEXP];

    int tid = threadIdx.x;
    int tx  = tid & 15;                // expert group (4 experts)
    int ty  = tid >> 4;                // token group  (8 tokens)
    int m0  = blockIdx.x * BM;

    double acc64[8][4];
#pragma unroll
    for (int i = 0; i < 8; i++)
#pragma unroll
        for (int j = 0; j < 4; j++) acc64[i][j] = 0.0;

    for (int k0 = 0; k0 < HID; k0 += BK) {
#pragma unroll
        for (int j = 0; j < 4; j++) {
            int idx = tid + j * 256;
            int m   = idx >> 3;
            int kq  = (idx & 7) << 2;
            float4 v = *(const float4*)(X + (size_t)(m0 + m) * HID + k0 + kq);
            *(float4*)&As[m][kq] = v;
        }
#pragma unroll
        for (int j = 0; j < 2; j++) {
            int idx = tid + j * 256;
            int e   = idx >> 3;
            int kq  = (idx & 7) << 2;
            float4 v = *(const float4*)(W + (size_t)e * HID + k0 + kq);
            Bs[kq + 0][e] = v.x; Bs[kq + 1][e] = v.y;
            Bs[kq + 2][e] = v.z; Bs[kq + 3][e] = v.w;
        }
        __syncthreads();

        float accf[8][4];
#pragma unroll
        for (int i = 0; i < 8; i++)
#pragma unroll
            for (int j = 0; j < 4; j++) accf[i][j] = 0.f;

#pragma unroll
        for (int k = 0; k < BK; k++) {
            float a[8];
#pragma unroll
            for (int i = 0; i < 8; i++) a[i] = As[ty * 8 + i][k];
            float4 bv = *(const float4*)&Bs[k][tx * 4];
            float b[4] = {bv.x, bv.y, bv.z, bv.w};
#pragma unroll
            for (int i = 0; i < 8; i++)
#pragma unroll
                for (int j = 0; j < 4; j++)
                    accf[i][j] = fmaf(a[i], b[j], accf[i][j]);
        }
        // promote chunk partials to fp64
#pragma unroll
        for (int i = 0; i < 8; i++)
#pragma unroll
            for (int j = 0; j < 4; j++) acc64[i][j] += (double)accf[i][j];
        __syncthreads();
    }

#pragma unroll
    for (int i = 0; i < 8; i++) {
        size_t t = (size_t)(m0 + ty * 8 + i);
#pragma unroll
        for (int j = 0; j < 4; j++)
            g_C[t * NEXP + tx * 4 + j] = __nv_expf((float)acc64[i][j]);
    }
}

// ---------------------------------------------------------------------------
// Grid barrier: monotonic 64-bit counter; 148 co-resident CTAs (1/SM).
// Counter is a multiple of GRIDB at launch boundaries -> graph-replay safe.
// ---------------------------------------------------------------------------
__device__ __forceinline__ void grid_barrier()
{
    __syncthreads();
    if (threadIdx.x == 0) {
        __threadfence();
        unsigned long long my = atomicAdd(&g_bar, 1ULL);
        unsigned long long target = (my / GRIDB + 1ULL) * GRIDB;
        for (;;) {
            unsigned long long cur;
            asm volatile("ld.global.acquire.gpu.u64 %0, [%1];" : "=l"(cur) : "l"(&g_bar));
            if (cur >= target) break;
            __nanosleep(64);
        }
    }
    __syncthreads();
}

__device__ __forceinline__ double warp_tree_add64(double s)
{
#pragma unroll
    for (int off = 16; off; off >>= 1)
        s += __shfl_xor_sync(0xffffffffu, s, off);
    return s;
}

// ---------------------------------------------------------------------------
// Kernel 2: persistent Sinkhorn + top-2 + softmax-gather, fp64 internals.
// C stays f32 (matches reference's f32 cost matrix); all reductions, d0/d1,
// err and the ranking comparison are fp64 -> my d1/ranking ~ exact, so the
// divergence vs reference collapses to the reference's own rounding error.
// ---------------------------------------------------------------------------
__global__ void __launch_bounds__(TPB)
sinkhorn_kernel(float* __restrict__ out, int out_size)
{
    __shared__ float  Cs[TOKB * NEXP];        // ~27.8 KB
    __shared__ double d1s[NEXP];              // current d1
    __shared__ double d1b[NEXP];              // next d1
    __shared__ double d1p[NEXP];              // d1 at entry of last iteration
    __shared__ double warp_part[8][NEXP];     // 4 KB
    __shared__ double s_err;

    const int tid  = threadIdx.x;
    const int bid  = blockIdx.x;
    const int lane = tid & 31;
    const int w    = tid >> 5;
    const int tok0 = bid * TOKB;
    const int ntok = min(TOKB, NTOK - tok0);

    for (int i = bid * TPB + tid; i < MAX_ITERS * NEXP; i += GRIDB * TPB)
        g_colsum[i] = 0.0;
    for (int i = tid; i < ntok * NEXP; i += TPB)
        Cs[i] = g_C[(size_t)tok0 * NEXP + i];
    if (tid < NEXP) { d1s[tid] = 1.0; d1p[tid] = 1.0; }
    grid_barrier();   // colsum zeros globally visible

    const double INVN0 = 1.0 / (double)NTOK;
    const double INVN1 = 1.0 / (double)NEXP;
    const double EPS64 = (double)1e-8f;       // exact value of the f32 eps

    for (int it = 0; it < MAX_ITERS; it++) {
        double d1a = d1s[lane];
        double d1c = d1s[lane + 32];
        double p0 = 0.0, p1 = 0.0;
        for (int t = w; t < ntok; t += 8) {
            double c0 = (double)Cs[t * NEXP + lane];
            double c1 = (double)Cs[t * NEXP + lane + 32];
            double s  = warp_tree_add64(d1a * c0 + d1c * c1);
            double d0 = INVN0 / (s + EPS64);
            p0 = fma(d0, c0, p0);
            p1 = fma(d0, c1, p1);
        }
        warp_part[w][lane]      = p0;
        warp_part[w][lane + 32] = p1;
        __syncthreads();
        if (tid < NEXP) {
            double sum = 0.0;
#pragma unroll
            for (int ww = 0; ww < 8; ww++) sum += warp_part[ww][tid];
            atomicAdd(&g_colsum[it * NEXP + tid], sum);
        }
        grid_barrier();

        if (tid < NEXP)
            d1b[tid] = INVN1 / (g_colsum[it * NEXP + tid] + EPS64);
        __syncthreads();
        if (w == 0) {   // err = mean |d1_old - d1_new|
            double a = fabs(d1s[lane]      - d1b[lane]);
            double b = fabs(d1s[lane + 32] - d1b[lane + 32]);
            double s = warp_tree_add64(a + b);
            if (lane == 0) s_err = s * INVN1;
        }
        __syncthreads();
        double err = s_err;
        if (tid < NEXP) { d1p[tid] = d1s[tid]; d1s[tid] = d1b[tid]; }
        __syncthreads();
        if (err <= SINK_TOL) break;     // identical decision in every block
    }

    // ---- final: top-2 of d1_final*C*d0_final;  scores = C / rowsum(C) ----
    double d1a = d1s[lane], d1c = d1s[lane + 32];
    double dpa = d1p[lane], dpc = d1p[lane + 32];
    for (int t = w; t < ntok; t += 8) {
        double c0 = (double)Cs[t * NEXP + lane];
        double c1 = (double)Cs[t * NEXP + lane + 32];
        double s  = d1a * 0.0;  (void)s;
        // d0 uses d1 entering the last executed iteration (= while_loop state)
        double sr = warp_tree_add64(dpa * c0 + dpc * c1);
        double rs = warp_tree_add64(c0 + c1);
        double d0 = INVN0 / (sr + EPS64);
        double v0 = (d1a * c0) * d0;
        double v1 = (d1c * c1) * d0;

        // argmax #1, ties -> lower index (jax top_k convention)
        double mv; int mi;
        if (v0 >= v1) { mv = v0; mi = lane; } else { mv = v1; mi = lane + 32; }
#pragma unroll
        for (int off = 16; off; off >>= 1) {
            double ov = __shfl_xor_sync(0xffffffffu, mv, off);
            int    oi = __shfl_xor_sync(0xffffffffu, mi, off);
            if (ov > mv || (ov == mv && oi < mi)) { mv = ov; mi = oi; }
        }
        // argmax #2 (exclude mi)
        double u0 = (lane      == mi) ? -1e308 : v0;
        double u1 = (lane + 32 == mi) ? -1e308 : v1;
        double mv2; int mi2;
        if (u0 >= u1) { mv2 = u0; mi2 = lane; } else { mv2 = u1; mi2 = lane + 32; }
#pragma unroll
        for (int off = 16; off; off >>= 1) {
            double ov = __shfl_xor_sync(0xffffffffu, mv2, off);
            int    oi = __shfl_xor_sync(0xffffffffu, mi2, off);
            if (ov > mv2 || (ov == mv2 && oi < mi2)) { mv2 = ov; mi2 = oi; }
        }

        if (lane == 0) {
            int tg = tok0 + t;
            float s0 = (float)((double)Cs[t * NEXP + mi]  / rs);
            float s1 = (float)((double)Cs[t * NEXP + mi2] / rs);
            if (out_size >= 4 * NTOK) {
                out[(size_t)tg * 2 + 0] = s0;
                out[(size_t)tg * 2 + 1] = s1;
                out[(size_t)2 * NTOK + tg * 2 + 0] = (float)mi;
                out[(size_t)2 * NTOK + tg * 2 + 1] = (float)mi2;
            } else {
                out[(size_t)tg * 2 + 0] = s0;
                out[(size_t)tg * 2 + 1] = s1;
            }
        }
    }
}

// ---------------------------------------------------------------------------
extern "C" void kernel_launch(void* const* d_in, const int* in_sizes, int n_in,
                              void* d_out, int out_size)
{
    const float* X = (const float*)d_in[0];
    const float* W = (const float*)d_in[1];
    if (n_in >= 2 && in_sizes[0] == NEXP * HID) {   // defensive input-order check
        X = (const float*)d_in[1];
        W = (const float*)d_in[0];
    }
    gemm_exp_kernel<<<NTOK / BM, 256>>>(X, W);
    sinkhorn_kernel<<<GRIDB, TPB>>>((float*)d_out, out_size);
}

// round 4
// speedup vs baseline: 3.7548x; 3.7548x over previous
#include <cuda_runtime.h>

#define HID   2048
#define NEXP  64
#define NTOK  16384
#define SINK_TOL 1e-4
#define MAX_ITERS 512
#define GRIDB 148
#define TPB   512
#define NW    (TPB / 32)
#define TOKB  111   // ceil(NTOK / GRIDB); 148*111 = 16428 >= 16384

// libdevice exp — what XLA GPU emits for jnp.exp, immune to fast-math rewrite.
extern "C" __device__ float __nv_expf(float);

// Scratch (static device arrays — no allocations).
__device__ unsigned long long g_bar = 0ULL;              // monotonic grid barrier
__device__ float  g_C[(size_t)NTOK * NEXP];              // exp(logits) f32, 4 MB
__device__ double g_colsum[MAX_ITERS * NEXP];            // per-iteration column sums (f64)

// ---------------------------------------------------------------------------
// Kernel 1: logits GEMM, pure f32.  Chunked accumulation: f32 FFMA chain
// inside each BK=64 k-chunk, chunk partials added into a second-level f32
// accumulator.  Total logit error ~3e-7 (vs reference's own ~1.4e-6).
// ---------------------------------------------------------------------------
#define BM 64
#define BK 64
#define LDPAD 68   // row stride in floats (16B-aligned, conflict-light)

__global__ void __launch_bounds__(256)
gemm_exp_kernel(const float* __restrict__ X, const float* __restrict__ W)
{
    __shared__ float As[BM][LDPAD];
    __shared__ float Bs[BK][LDPAD];   // [k][expert], transposed scatter

    int tid = threadIdx.x;
    int tx  = tid & 15;               // expert group (4 experts)
    int ty  = tid >> 4;               // token group  (4 tokens)
    int m0  = blockIdx.x * BM;

    float hi[4][4];
#pragma unroll
    for (int i = 0; i < 4; i++)
#pragma unroll
        for (int j = 0; j < 4; j++) hi[i][j] = 0.f;

    for (int k0 = 0; k0 < HID; k0 += BK) {
        // A tile: 64x64 floats = 1024 float4, 4 per thread
#pragma unroll
        for (int j = 0; j < 4; j++) {
            int idx = tid + j * 256;
            int m   = idx >> 4;
            int kq  = (idx & 15) << 2;
            float4 v = *(const float4*)(X + (size_t)(m0 + m) * HID + k0 + kq);
            *(float4*)&As[m][kq] = v;
        }
        // B tile: 64 experts x 64 k = 1024 float4, 4 per thread, k-major scatter
#pragma unroll
        for (int j = 0; j < 4; j++) {
            int idx = tid + j * 256;
            int e   = idx >> 4;
            int kq  = (idx & 15) << 2;
            float4 v = *(const float4*)(W + (size_t)e * HID + k0 + kq);
            Bs[kq + 0][e] = v.x; Bs[kq + 1][e] = v.y;
            Bs[kq + 2][e] = v.z; Bs[kq + 3][e] = v.w;
        }
        __syncthreads();

        float accf[4][4];
#pragma unroll
        for (int i = 0; i < 4; i++)
#pragma unroll
            for (int j = 0; j < 4; j++) accf[i][j] = 0.f;

#pragma unroll 16
        for (int k = 0; k < BK; k++) {
            float a[4];
#pragma unroll
            for (int i = 0; i < 4; i++) a[i] = As[ty * 4 + i][k];
            float4 bv = *(const float4*)&Bs[k][tx * 4];
            float b[4] = {bv.x, bv.y, bv.z, bv.w};
#pragma unroll
            for (int i = 0; i < 4; i++)
#pragma unroll
                for (int j = 0; j < 4; j++)
                    accf[i][j] = fmaf(a[i], b[j], accf[i][j]);
        }
        // promote chunk partials into second-level f32 accumulator
#pragma unroll
        for (int i = 0; i < 4; i++)
#pragma unroll
            for (int j = 0; j < 4; j++) hi[i][j] += accf[i][j];
        __syncthreads();
    }

#pragma unroll
    for (int i = 0; i < 4; i++) {
        size_t t = (size_t)(m0 + ty * 4 + i);
        float4 o;
        o.x = __nv_expf(hi[i][0]); o.y = __nv_expf(hi[i][1]);
        o.z = __nv_expf(hi[i][2]); o.w = __nv_expf(hi[i][3]);
        *(float4*)&g_C[t * NEXP + tx * 4] = o;
    }
}

// ---------------------------------------------------------------------------
// Grid barrier: monotonic 64-bit counter; 148 co-resident CTAs (1/SM).
// Counter is a multiple of GRIDB at launch boundaries -> graph-replay safe.
// ---------------------------------------------------------------------------
__device__ __forceinline__ void grid_barrier()
{
    __syncthreads();
    if (threadIdx.x == 0) {
        __threadfence();
        unsigned long long my = atomicAdd(&g_bar, 1ULL);
        unsigned long long target = (my / GRIDB + 1ULL) * GRIDB;
        for (;;) {
            unsigned long long cur;
            asm volatile("ld.global.acquire.gpu.u64 %0, [%1];" : "=l"(cur) : "l"(&g_bar));
            if (cur >= target) break;
        }
    }
    __syncthreads();
}

__device__ __forceinline__ double warp_tree_add64(double s)
{
#pragma unroll
    for (int off = 16; off; off >>= 1)
        s += __shfl_xor_sync(0xffffffffu, s, off);
    return s;
}

// ---------------------------------------------------------------------------
// Kernel 2: persistent Sinkhorn + top-2 + softmax-gather.
// Row pass (rowsum, d0, colsum partials) in f32 — the per-token d0 rounding
// (~1.5e-7 rel) averages out over 16384 tokens in the colsum (d1 error ~1e-9).
// d1 / err / final ranking stay fp64 -> divergence vs reference collapses to
// the reference's own f32 rounding error, as in R3.
// ---------------------------------------------------------------------------
__global__ void __launch_bounds__(TPB)
sinkhorn_kernel(float* __restrict__ out, int out_size)
{
    __shared__ float  Cs[TOKB * NEXP];        // ~27.8 KB
    __shared__ double d1d[NEXP];              // current d1 (f64 master)
    __shared__ double d1b[NEXP];              // next d1
    __shared__ double d1pd[NEXP];             // d1 at entry of last iteration
    __shared__ float  d1f[NEXP];              // f32 mirror for the row pass
    __shared__ float  warp_part[NW][NEXP];    // 4 KB
    __shared__ double s_err;

    const int tid  = threadIdx.x;
    const int bid  = blockIdx.x;
    const int lane = tid & 31;
    const int w    = tid >> 5;
    const int tok0 = bid * TOKB;
    const int ntok = min(TOKB, NTOK - tok0);

    for (int i = bid * TPB + tid; i < MAX_ITERS * NEXP; i += GRIDB * TPB)
        g_colsum[i] = 0.0;
    {   // vectorized stage of this block's C slice
        const float4* src = (const float4*)(g_C + (size_t)tok0 * NEXP);
        float4* dst = (float4*)Cs;
        for (int i = tid; i < ntok * (NEXP / 4); i += TPB) dst[i] = src[i];
    }
    if (tid < NEXP) { d1d[tid] = 1.0; d1pd[tid] = 1.0; d1f[tid] = 1.f; }
    grid_barrier();   // colsum zeros globally visible

    const float  INVN0F = 1.0f / (float)NTOK;   // 2^-14 exact
    const float  EPSF   = 1e-8f;
    const double INVN1D = 1.0 / (double)NEXP;
    const double EPSD   = (double)1e-8f;

    for (int it = 0; it < MAX_ITERS; it++) {
        float d1a = d1f[lane];
        float d1c = d1f[lane + 32];
        float p0 = 0.f, p1 = 0.f;
        for (int t = w; t < ntok; t += NW) {
            float c0 = Cs[t * NEXP + lane];
            float c1 = Cs[t * NEXP + lane + 32];
            float s  = fmaf(d1a, c0, d1c * c1);
#pragma unroll
            for (int off = 16; off; off >>= 1)
                s += __shfl_xor_sync(0xffffffffu, s, off);
            float d0 = INVN0F / (s + EPSF);
            p0 = fmaf(d0, c0, p0);
            p1 = fmaf(d0, c1, p1);
        }
        warp_part[w][lane]      = p0;
        warp_part[w][lane + 32] = p1;
        __syncthreads();
        if (tid < NEXP) {
            double sum = 0.0;
#pragma unroll
            for (int ww = 0; ww < NW; ww++) sum += (double)warp_part[ww][tid];
            atomicAdd(&g_colsum[it * NEXP + tid], sum);
        }
        grid_barrier();

        if (tid < NEXP)
            d1b[tid] = INVN1D / (g_colsum[it * NEXP + tid] + EPSD);
        __syncthreads();
        if (w == 0) {   // err = mean |d1_old - d1_new| (fp64)
            double a = fabs(d1d[lane]      - d1b[lane]);
            double b = fabs(d1d[lane + 32] - d1b[lane + 32]);
            double s = warp_tree_add64(a + b);
            if (lane == 0) s_err = s * INVN1D;
        }
        __syncthreads();
        double err = s_err;
        if (tid < NEXP) {
            d1pd[tid] = d1d[tid];
            d1d[tid]  = d1b[tid];
            d1f[tid]  = (float)d1b[tid];
        }
        __syncthreads();
        if (err <= SINK_TOL) break;     // identical decision in every block
    }

    // ---- final: top-2 of d1_final*C*d0_final (fp64);  scores = C/rowsum(C) --
    const double INVN0D = 1.0 / (double)NTOK;
    double d1a = d1d[lane], d1c = d1d[lane + 32];
    double dpa = d1pd[lane], dpc = d1pd[lane + 32];
    for (int t = w; t < ntok; t += NW) {
        double c0 = (double)Cs[t * NEXP + lane];
        double c1 = (double)Cs[t * NEXP + lane + 32];
        // d0 uses d1 entering the last executed iteration (= while_loop state)
        double sr = warp_tree_add64(dpa * c0 + dpc * c1);
        double rs = warp_tree_add64(c0 + c1);
        double d0 = INVN0D / (sr + EPSD);
        double v0 = (d1a * c0) * d0;
        double v1 = (d1c * c1) * d0;

        // argmax #1, ties -> lower index (jax top_k convention)
        double mv; int mi;
        if (v0 >= v1) { mv = v0; mi = lane; } else { mv = v1; mi = lane + 32; }
#pragma unroll
        for (int off = 16; off; off >>= 1) {
            double ov = __shfl_xor_sync(0xffffffffu, mv, off);
            int    oi = __shfl_xor_sync(0xffffffffu, mi, off);
            if (ov > mv || (ov == mv && oi < mi)) { mv = ov; mi = oi; }
        }
        // argmax #2 (exclude mi)
        double u0 = (lane      == mi) ? -1e308 : v0;
        double u1 = (lane + 32 == mi) ? -1e308 : v1;
        double mv2; int mi2;
        if (u0 >= u1) { mv2 = u0; mi2 = lane; } else { mv2 = u1; mi2 = lane + 32; }
#pragma unroll
        for (int off = 16; off; off >>= 1) {
            double ov = __shfl_xor_sync(0xffffffffu, mv2, off);
            int    oi = __shfl_xor_sync(0xffffffffu, mi2, off);
            if (ov > mv2 || (ov == mv2 && oi < mi2)) { mv2 = ov; mi2 = oi; }
        }

        if (lane == 0) {
            int tg = tok0 + t;
            float s0 = (float)((double)Cs[t * NEXP + mi]  / rs);
            float s1 = (float)((double)Cs[t * NEXP + mi2] / rs);
            if (out_size >= 4 * NTOK) {
                out[(size_t)tg * 2 + 0] = s0;
                out[(size_t)tg * 2 + 1] = s1;
                out[(size_t)2 * NTOK + tg * 2 + 0] = (float)mi;
                out[(size_t)2 * NTOK + tg * 2 + 1] = (float)mi2;
            } else {
                out[(size_t)tg * 2 + 0] = s0;
                out[(size_t)tg * 2 + 1] = s1;
            }
        }
    }
}

// ---------------------------------------------------------------------------
extern "C" void kernel_launch(void* const* d_in, const int* in_sizes, int n_in,
                              void* d_out, int out_size)
{
    const float* X = (const float*)d_in[0];
    const float* W = (const float*)d_in[1];
    if (n_in >= 2 && in_sizes[0] == NEXP * HID) {   // defensive input-order check
        X = (const float*)d_in[1];
        W = (const float*)d_in[0];
    }
    gemm_exp_kernel<<<NTOK / BM, 256>>>(X, W);
    sinkhorn_kernel<<<GRIDB, TPB>>>((float*)d_out, out_size);
}